// round 8
// baseline (speedup 1.0000x reference)
#include <cuda_runtime.h>
#include <math.h>

#define BATCH 64
#define CIN 32
#define T_IN 2048
#define FIL 64
#define WIN 5
#define T1 2044
#define T2 2040
#define LL 2036
#define DA 64
#define DD 256
#define SEC 11
#define BN_EPSF 1e-5f

#define TILE 128        // pooled outputs per k1 block
#define INT_ 136        // input positions per k1 tile
#define NTILE1 16       // k1 tiles over T2
#define TILE3 128       // l positions per k3 block
#define NTILE3 16       // k3 tiles over LL
#define JP 68           // padded a-stride for sGT in k5
#define LHALF 1018      // LL/2 for k4

// ---------------- scratch (device globals) ----------------
__device__ float g_h2[BATCH * T2 * FIL];            // pooled conv1 out, [b][t][f]
__device__ float g_part[NTILE1 * BATCH * FIL * 2];  // per-block BN partials
__device__ float g_we2[FIL * WIN];
__device__ float g_cterm;
__device__ int   g_idx[BATCH * LL];
__device__ float g_W1T[LL * DA];                    // W1 transposed [l][a]
__device__ float g_w1T[CIN * WIN * FIL];            // conv1 w transposed [c][k][f]
__device__ float g_Gc[BATCH * DD * DA];             // compact G [b][jj][a]
__device__ int   g_jlist[BATCH * DD];
__device__ int   g_nact[BATCH];
__device__ int   g_cnt[BATCH * DD];
__device__ float g_A[BATCH * DD];

// ---------------- K0: transposes ----------------
extern "C" __global__ void k0_prep(const float* __restrict__ W1,
                                   const float* __restrict__ w1) {
    int t = blockIdx.x * 256 + threadIdx.x;
    if (t < LL * DA) {
        int l = t >> 6, a = t & 63;
        g_W1T[t] = W1[a * LL + l];
    }
    int u = t - LL * DA;
    if (u >= 0 && u < CIN * WIN * FIL) {
        int f = u & 63, ck = u >> 6;          // ck = c*5+k
        g_w1T[u] = w1[f * (CIN * WIN) + ck];
    }
}

// ---------------- K1: conv1 + maxpool5 + BN partials  (UNCHANGED / validated) -
extern "C" __global__ void __launch_bounds__(256, 3)
k1_conv_pool(const float* __restrict__ x, const float* __restrict__ b1) {
    extern __shared__ float sm[];
    float* sx  = sm;                    // CIN*INT_  (4352)
    float* sp  = sx + CIN * INT_;       // TILE*FIL  (8192) layout [p][f]
    float* sst = sp + TILE * FIL;       // 8*32*2    (512)

    int tile = blockIdx.x, b = blockIdx.y;
    int t0 = tile * TILE;
    int tid = threadIdx.x;
    int w = tid >> 5, lane = tid & 31;
    int q = w >> 1, fhi = w & 1;
    int f = fhi * 32 + lane;
    int npool = min(TILE, T2 - t0);

    for (int i = tid; i < CIN * INT_; i += 256) {
        int c = i / INT_, p = i - c * INT_;
        int g = t0 + p;
        sx[i] = (g < T_IN) ? x[(b * CIN + c) * T_IN + g] : 0.f;
    }
    __syncthreads();

    float acc[36];
    float bias = __ldg(&b1[f]);
#pragma unroll
    for (int i = 0; i < 36; ++i) acc[i] = bias;

    int base = q * 32;
    for (int c = 0; c < CIN; ++c) {
        const float* wr = g_w1T + c * WIN * FIL + f;
        float w0 = __ldg(wr), wa = __ldg(wr + FIL), wb = __ldg(wr + 2 * FIL),
              wc = __ldg(wr + 3 * FIL), wd = __ldg(wr + 4 * FIL);
        const float* xr = sx + c * INT_ + base;
        float x0 = xr[0], x1 = xr[1], x2 = xr[2], x3 = xr[3];
#pragma unroll
        for (int i = 0; i < 36; ++i) {
            float x4 = xr[i + 4];
            acc[i] += w0 * x0 + wa * x1 + wb * x2 + wc * x3 + wd * x4;
            x0 = x1; x1 = x2; x2 = x3; x3 = x4;
        }
    }

    float ls = 0.f, ls2 = 0.f;
#pragma unroll
    for (int i = 0; i < 32; ++i) {
        float m = acc[i];
        m = fmaxf(m, acc[i + 1]); m = fmaxf(m, acc[i + 2]);
        m = fmaxf(m, acc[i + 3]); m = fmaxf(m, acc[i + 4]);
        int p = base + i;
        sp[p * FIL + f] = m;
        if (p < npool) { ls += m; ls2 += m * m; }
    }
    sst[(w * 32 + lane) * 2 + 0] = ls;
    sst[(w * 32 + lane) * 2 + 1] = ls2;
    __syncthreads();

    if (tid < FIL) {
        int fh = tid >> 5, ln = tid & 31;
        float s = 0.f, s2 = 0.f;
        for (int qq = 0; qq < 4; ++qq) {
            int ww = qq * 2 + fh;
            s  += sst[(ww * 32 + ln) * 2 + 0];
            s2 += sst[(ww * 32 + ln) * 2 + 1];
        }
        int blk = b * NTILE1 + tile;
        g_part[(blk * FIL + tid) * 2 + 0] = s;
        g_part[(blk * FIL + tid) * 2 + 1] = s2;
    }

    for (int o = tid; o < FIL * TILE; o += 256) {
        int p = o >> 6;
        if (p < npool)
            g_h2[((size_t)b * T2 + t0 + p) * FIL + (o & 63)] = sp[o];
    }
}

// ---------------- K2: reduce BN stats (UNCHANGED / validated) ----------------
extern "C" __global__ void k2_stats(const float* __restrict__ w2,
                                    const float* __restrict__ b2,
                                    const float* __restrict__ gamma,
                                    const float* __restrict__ beta) {
    __shared__ double ssum[256], ssum2[256];
    __shared__ float sct[FIL];
    int tid = threadIdx.x;  // 256
    int f = tid & 63, seg = tid >> 6;
    double s = 0.0, s2 = 0.0;
    for (int blk = seg; blk < NTILE1 * BATCH; blk += 4) {
        s  += (double)g_part[(blk * FIL + f) * 2 + 0];
        s2 += (double)g_part[(blk * FIL + f) * 2 + 1];
    }
    ssum[tid] = s; ssum2[tid] = s2;
    __syncthreads();
    if (seg == 0) {
        for (int k = 1; k < 4; ++k) { s += ssum[f + 64 * k]; s2 += ssum2[f + 64 * k]; }
        double N = (double)BATCH * (double)T2;
        double mud = s / N;
        float mu = (float)mud;
        float var = (float)(s2 / N - mud * mud);
        float scale = gamma[f] * rsqrtf(var + BN_EPSF);
        float shift = beta[f] - mu * scale;
        float wsum = 0.f;
        for (int k = 0; k < WIN; ++k) {
            float wv = w2[f * WIN + k];
            g_we2[f * WIN + k] = wv * scale;
            wsum += wv;
        }
        sct[f] = shift * wsum;
    }
    __syncthreads();
    if (tid == 0) {
        float c = b2[0];
        for (int i = 0; i < FIL; ++i) c += sct[i];
        g_cterm = c;
    }
}

// ---------------- K3: conv2 + relu + sigmoid + bucket index ------------------
// TILE3=128, 128 threads: smem 35.6 KB -> 6 CTAs/SM (was 3) for latency hiding.
// Per-l arithmetic expression is BITWISE IDENTICAL to the validated R7 form.
extern "C" __global__ void k3_conv2_idx() {
    extern __shared__ float sm3[];
    float* sh  = sm3;                     // (TILE3+4)*65  layout [t][f] pad
    float* swe = sh + (TILE3 + 4) * 65;   // FIL*WIN
    __shared__ float sct;
    int tile = blockIdx.x, b = blockIdx.y;
    int t0 = tile * TILE3;
    int tid = threadIdx.x;  // 128

    for (int o = tid; o < (TILE3 + 4) * FIL; o += 128) {
        int tl = o >> 6, ff = o & 63;
        int t = t0 + tl;
        sh[tl * 65 + ff] = (t < T2) ? g_h2[((size_t)b * T2 + t) * FIL + ff] : 0.f;
    }
    for (int o = tid; o < FIL * WIN; o += 128) swe[o] = g_we2[o];
    if (tid == 0) sct = g_cterm;
    __syncthreads();

    int l = t0 + tid;
    if (l < LL) {
        float z = sct;
#pragma unroll 8
        for (int f = 0; f < FIL; ++f) {
            const float* hr = sh + tid * 65 + f;   // h[t=tid+k][f] at hr + 65k
            const float* wr = swe + f * WIN;
            z += wr[0] * hr[0] + wr[1] * hr[65] + wr[2] * hr[130]
               + wr[3] * hr[195] + wr[4] * hr[260];
        }
        z = fmaxf(z, 0.f);
        float c = 1.f / (1.f + expf(-z));
        int iv = (int)ceilf(c * 256.f) - 1;
        iv = max(0, min(255, iv));
        g_idx[b * LL + l] = iv;
    }
}

// ---------------- K4: ATOMIC-FREE bucket scatter + compaction ----------------
// 128 threads = 2 l-halves x 64 a-rows. Each thread exclusively owns row
// (half, a) of a private smem copy -> plain LDS/STS run-length accumulate,
// no ATOMS at all. idx staged in smem (broadcast reads). Halves merged, then
// occupancy flags scan-compacted (pairwise Hillis-Steele, 128 thr / 256 j).
extern "C" __global__ void k4_scatter() {
    extern __shared__ float sm4[];
    float* sG   = sm4;                         // 2 * 64 * 257 floats
    int* sidx   = (int*)(sG + 2 * 64 * 257);   // LL (2036)
    int* shist  = sidx + LL;                   // 2 * 256
    int* sscan  = shist + 2 * 256;             // 128
    int* spos   = sscan + 128;                 // 256
    int b = blockIdx.x;
    int tid = threadIdx.x;  // 128
    int h = tid >> 6, a = tid & 63;

    for (int o = tid; o < 2 * 64 * 257; o += 128) sG[o] = 0.f;
    for (int o = tid; o < LL; o += 128) sidx[o] = g_idx[b * LL + o];
    for (int o = tid; o < 2 * 256; o += 128) shist[o] = 0;
    __syncthreads();

    // run-length walk: exclusive ownership -> non-atomic smem RMW
    {
        float* row = sG + (h * 64 + a) * 257;
        int* hist = shist + h * 256;
        int l0 = h * LHALF, l1 = l0 + LHALF;
        int jprev = -1, cacc = 0;
        float wacc = 0.f;
#pragma unroll 4
        for (int l = l0; l < l1; ++l) {
            int j = sidx[l];                       // broadcast LDS
            float wv = g_W1T[l * DA + a];          // coalesced LDG
            if (j != jprev) {                      // warp-uniform branch
                if (jprev >= 0) {
                    row[jprev] += wacc;
                    if (a == 0) hist[jprev] += cacc;
                }
                jprev = j; wacc = wv; cacc = 1;
            } else { wacc += wv; ++cacc; }
        }
        if (jprev >= 0) {
            row[jprev] += wacc;
            if (a == 0) hist[jprev] += cacc;
        }
    }
    __syncthreads();

    // merge halves: G row-major [a][j] in copy 0; hist into shist[0..255]
    for (int o = tid; o < 64 * 256; o += 128) {
        int aa = o >> 8, j = o & 255;
        sG[aa * 257 + j] += sG[(64 + aa) * 257 + j];
    }
    for (int j = tid; j < 256; j += 128) {
        int c = shist[j] + shist[256 + j];
        shist[j] = c;
        g_cnt[b * DD + j] = c;
    }
    __syncthreads();

    // pairwise scan: thread t owns j = 2t, 2t+1
    int j0 = 2 * tid, j1 = 2 * tid + 1;
    int f0 = (shist[j0] > 0) ? 1 : 0;
    int f1 = (shist[j1] > 0) ? 1 : 0;
    int p = f0 + f1;
    sscan[tid] = p;
    __syncthreads();
    for (int off = 1; off < 128; off <<= 1) {
        int add = (tid >= off) ? sscan[tid - off] : 0;
        __syncthreads();
        sscan[tid] += add;
        __syncthreads();
    }
    int E = sscan[tid] - p;
    spos[j0] = E;
    spos[j1] = E + f0;
    if (f0) g_jlist[b * DD + E] = j0;
    if (f1) g_jlist[b * DD + E + f0] = j1;
    if (tid == 127) g_nact[b] = sscan[127];
    __syncthreads();

    // compact write of active-bucket G rows: Gc[b][jj][a]
    for (int o = tid; o < 64 * 256; o += 128) {
        int j = o >> 6, aa = o & 63;
        if (shist[j] > 0)
            g_Gc[((size_t)b * DD + spos[j]) * DA + aa] = sG[aa * 257 + j];
    }
}

// ---------------- K5: t = tanh(Gc @ emb_active); A = W2^T t ----------------
extern "C" __global__ void k5_gemm(const float* __restrict__ emb,
                                   const float* __restrict__ W2) {
    extern __shared__ float sm5[];
    float* sGT = sm5;                   // DD*JP (only nact rows used)
    float* sA  = sGT + DD * JP;         // 128
    float* sW2 = sA + 128;              // 64
    int*   sjl = (int*)(sW2 + DA);      // 256
    int b = blockIdx.x, half = blockIdx.y;
    int tid = threadIdx.x;  // 128

    int nact = g_nact[b];
    for (int o = tid; o < nact * DA; o += 128) {
        int jj = o >> 6, a = o & 63;
        sGT[jj * JP + a] = g_Gc[((size_t)b * DD + jj) * DA + a];
    }
    for (int o = tid; o < DD; o += 128) sjl[o] = g_jlist[b * DD + o];
    sA[tid] = 0.f;
    if (tid < DA) sW2[tid] = W2[tid];
    __syncthreads();

    int ta = tid >> 4, td = tid & 15;   // 8 x 16
    int a0 = ta * 8;
    int d0 = half * 128 + td * 8;
    float acc[8][8];
#pragma unroll
    for (int r = 0; r < 8; ++r)
#pragma unroll
        for (int s = 0; s < 8; ++s) acc[r][s] = 0.f;

    for (int jj = 0; jj < nact; ++jj) {
        const float* er = emb + (size_t)sjl[jj] * DD + d0;
        float4 ga = *(const float4*)&sGT[jj * JP + a0];
        float4 gb = *(const float4*)&sGT[jj * JP + a0 + 4];
        float4 e0 = __ldg((const float4*)er);
        float4 e1 = __ldg((const float4*)(er + 4));
        float gv[8] = {ga.x, ga.y, ga.z, ga.w, gb.x, gb.y, gb.z, gb.w};
        float ev[8] = {e0.x, e0.y, e0.z, e0.w, e1.x, e1.y, e1.z, e1.w};
#pragma unroll
        for (int r = 0; r < 8; ++r)
#pragma unroll
            for (int s = 0; s < 8; ++s)
                acc[r][s] = fmaf(gv[r], ev[s], acc[r][s]);
    }

    float pA[8];
#pragma unroll
    for (int s = 0; s < 8; ++s) pA[s] = 0.f;
#pragma unroll
    for (int r = 0; r < 8; ++r) {
        float wv = sW2[a0 + r];
#pragma unroll
        for (int s = 0; s < 8; ++s)
            pA[s] = fmaf(wv, tanhf(acc[r][s]), pA[s]);
    }
#pragma unroll
    for (int s = 0; s < 8; ++s)
        atomicAdd(&sA[td * 8 + s], pA[s]);
    __syncthreads();
    g_A[b * DD + half * 128 + tid] = sA[tid];
}

// ---------------- K6: bucket softmax + att gather + scores ----------------
extern "C" __global__ void k6_final(const float* __restrict__ emb,
                                    const float* __restrict__ lin_w,
                                    const float* __restrict__ lin_b,
                                    float* __restrict__ out) {
    __shared__ float sA[DD];
    __shared__ float sE[DD];
    __shared__ float red[256];
    int b = blockIdx.x;
    int tid = threadIdx.x;  // 256
    sA[tid] = g_A[b * DD + tid];
    __syncthreads();

    int j = tid;
    float P = 0.f;
    const float4* er = (const float4*)(emb + (size_t)j * DD);
#pragma unroll 8
    for (int d4 = 0; d4 < DD / 4; ++d4) {
        float4 e = __ldg(er + d4);
        P += e.x * sA[d4 * 4 + 0] + e.y * sA[d4 * 4 + 1]
           + e.z * sA[d4 * 4 + 2] + e.w * sA[d4 * 4 + 3];
    }
    int cj = g_cnt[b * DD + j];
    red[tid] = (cj > 0) ? P : -3.0e38f;
    __syncthreads();
    for (int st = 128; st > 0; st >>= 1) {
        if (tid < st) red[tid] = fmaxf(red[tid], red[tid + st]);
        __syncthreads();
    }
    float m = red[0];
    __syncthreads();
    float ex = (cj > 0) ? expf(P - m) : 0.f;
    red[tid] = (float)cj * ex;
    __syncthreads();
    for (int st = 128; st > 0; st >>= 1) {
        if (tid < st) red[tid] += red[tid + st];
        __syncthreads();
    }
    float Z = red[0];
    sE[j] = ex / Z;
    __syncthreads();

    for (int l = tid; l < LL; l += 256)
        out[b * LL + l] = sE[g_idx[b * LL + l]];

    if (tid < SEC) {
        float s = lin_b[tid];
        const float* wr = lin_w + tid * DD;
        for (int d = 0; d < DD; ++d) s += wr[d] * sA[d];
        out[BATCH * LL + b * SEC + tid] = s;
    }
}

// ---------------- launch ----------------
extern "C" void kernel_launch(void* const* d_in, const int* in_sizes, int n_in,
                              void* d_out, int out_size) {
    const float* x     = (const float*)d_in[0];
    const float* c1w   = (const float*)d_in[1];
    const float* c1b   = (const float*)d_in[2];
    const float* gamma = (const float*)d_in[3];
    const float* beta  = (const float*)d_in[4];
    const float* c2w   = (const float*)d_in[5];
    const float* c2b   = (const float*)d_in[6];
    const float* emb   = (const float*)d_in[7];
    const float* W1    = (const float*)d_in[8];
    const float* W2    = (const float*)d_in[9];
    const float* lw    = (const float*)d_in[10];
    const float* lb    = (const float*)d_in[11];
    float* out = (float*)d_out;

    size_t sm1 = (size_t)(CIN * INT_ + TILE * FIL + 8 * 32 * 2) * sizeof(float);
    size_t sm3 = (size_t)((TILE3 + 4) * 65 + FIL * WIN) * sizeof(float);
    size_t sm4 = (size_t)(2 * 64 * 257) * sizeof(float)
               + (size_t)(LL + 2 * 256 + 128 + 256) * sizeof(int);
    size_t sm5 = (size_t)(DD * JP + 128 + DA) * sizeof(float) + DD * sizeof(int);
    cudaFuncSetAttribute(k1_conv_pool, cudaFuncAttributeMaxDynamicSharedMemorySize, (int)sm1);
    cudaFuncSetAttribute(k3_conv2_idx, cudaFuncAttributeMaxDynamicSharedMemorySize, (int)sm3);
    cudaFuncSetAttribute(k4_scatter,   cudaFuncAttributeMaxDynamicSharedMemorySize, (int)sm4);
    cudaFuncSetAttribute(k5_gemm,      cudaFuncAttributeMaxDynamicSharedMemorySize, (int)sm5);

    int n0 = LL * DA + CIN * WIN * FIL;
    k0_prep<<<(n0 + 255) / 256, 256>>>(W1, c1w);
    k1_conv_pool<<<dim3(NTILE1, BATCH), 256, sm1>>>(x, c1b);
    k2_stats<<<1, 256>>>(c2w, c2b, gamma, beta);
    k3_conv2_idx<<<dim3(NTILE3, BATCH), 128, sm3>>>();
    k4_scatter<<<BATCH, 128, sm4>>>();
    k5_gemm<<<dim3(BATCH, 2), 128, sm5>>>(emb, W2);
    k6_final<<<BATCH, 256>>>(emb, lw, lb, out);
}

// round 10
// speedup vs baseline: 1.1800x; 1.1800x over previous
#include <cuda_runtime.h>
#include <math.h>

#define BATCH 64
#define CIN 32
#define T_IN 2048
#define FIL 64
#define WIN 5
#define T1 2044
#define T2 2040
#define LL 2036
#define DA 64
#define DD 256
#define SEC 11
#define BN_EPSF 1e-5f

#define TILE 128        // pooled outputs per k1 block
#define INT_ 136        // input positions per k1 tile
#define NTILE1 16       // k1 tiles over T2
#define TILE3 128       // l positions per k3 block
#define NTILE3 16       // k3 tiles over LL
#define JP 68           // padded a-stride for sGT in k5
#define LQ 509          // l's per k4a quarter (4*509 = 2036)

// ---------------- scratch (device globals) ----------------
__device__ float g_h2[BATCH * T2 * FIL];            // pooled conv1 out, [b][t][f]
__device__ float g_part[NTILE1 * BATCH * FIL * 2];  // per-block BN partials
__device__ float g_we2[FIL * WIN];
__device__ float g_cterm;
__device__ int   g_idx[BATCH * LL];
__device__ float g_W1T[LL * DA];                    // W1 transposed [l][a]
__device__ float g_w1T[CIN * WIN * FIL];            // conv1 w transposed [c][k][f]
__device__ float g_Gpart[(size_t)BATCH * 4 * DA * DD]; // per-quarter partial G
__device__ int   g_hpart[BATCH * 4 * DD];           // per-quarter partial hist
__device__ float g_Gc[BATCH * DD * DA];             // compact G [b][jj][a]
__device__ int   g_jlist[BATCH * DD];
__device__ int   g_nact[BATCH];
__device__ int   g_cnt[BATCH * DD];
__device__ float g_A[BATCH * DD];

// ---------------- K0: transposes ----------------
extern "C" __global__ void k0_prep(const float* __restrict__ W1,
                                   const float* __restrict__ w1) {
    int t = blockIdx.x * 256 + threadIdx.x;
    if (t < LL * DA) {
        int l = t >> 6, a = t & 63;
        g_W1T[t] = W1[a * LL + l];
    }
    int u = t - LL * DA;
    if (u >= 0 && u < CIN * WIN * FIL) {
        int f = u & 63, ck = u >> 6;          // ck = c*5+k
        g_w1T[u] = w1[f * (CIN * WIN) + ck];
    }
}

// ---------------- K1: conv1 + maxpool5 + BN partials ------------------------
// Arithmetic (acc expression, pooling, stats order) BITWISE IDENTICAL to the
// validated R7 kernel. Change: pooled values stored straight from registers
// to g_h2 (per-i, warp lanes span 32 consecutive f -> coalesced 128B STG);
// removes the 32KB sp staging buffer + one sync. smem 52KB -> 19KB.
extern "C" __global__ void __launch_bounds__(256)
k1_conv_pool(const float* __restrict__ x, const float* __restrict__ b1) {
    extern __shared__ float sm[];
    float* sx  = sm;                    // CIN*INT_  (4352)
    float* sst = sx + CIN * INT_;       // 8*32*2    (512)

    int tile = blockIdx.x, b = blockIdx.y;
    int t0 = tile * TILE;
    int tid = threadIdx.x;
    int w = tid >> 5, lane = tid & 31;
    int q = w >> 1, fhi = w & 1;
    int f = fhi * 32 + lane;
    int npool = min(TILE, T2 - t0);

    for (int i = tid; i < CIN * INT_; i += 256) {
        int c = i / INT_, p = i - c * INT_;
        int g = t0 + p;
        sx[i] = (g < T_IN) ? x[(b * CIN + c) * T_IN + g] : 0.f;
    }
    __syncthreads();

    float acc[36];
    float bias = __ldg(&b1[f]);
#pragma unroll
    for (int i = 0; i < 36; ++i) acc[i] = bias;

    int base = q * 32;
    for (int c = 0; c < CIN; ++c) {
        const float* wr = g_w1T + c * WIN * FIL + f;
        float w0 = __ldg(wr), wa = __ldg(wr + FIL), wb = __ldg(wr + 2 * FIL),
              wc = __ldg(wr + 3 * FIL), wd = __ldg(wr + 4 * FIL);
        const float* xr = sx + c * INT_ + base;
        float x0 = xr[0], x1 = xr[1], x2 = xr[2], x3 = xr[3];
#pragma unroll
        for (int i = 0; i < 36; ++i) {
            float x4 = xr[i + 4];
            acc[i] += w0 * x0 + wa * x1 + wb * x2 + wc * x3 + wd * x4;
            x0 = x1; x1 = x2; x2 = x3; x3 = x4;
        }
    }

    // pool + stats in registers; direct coalesced store of valid positions
    float ls = 0.f, ls2 = 0.f;
    float* h2row = g_h2 + ((size_t)b * T2 + t0) * FIL + f;
#pragma unroll
    for (int i = 0; i < 32; ++i) {
        float m = acc[i];
        m = fmaxf(m, acc[i + 1]); m = fmaxf(m, acc[i + 2]);
        m = fmaxf(m, acc[i + 3]); m = fmaxf(m, acc[i + 4]);
        int p = base + i;
        if (p < npool) {
            h2row[(size_t)p * FIL] = m;
            ls += m; ls2 += m * m;
        }
    }
    sst[(w * 32 + lane) * 2 + 0] = ls;
    sst[(w * 32 + lane) * 2 + 1] = ls2;
    __syncthreads();

    if (tid < FIL) {
        int fh = tid >> 5, ln = tid & 31;
        float s = 0.f, s2 = 0.f;
        for (int qq = 0; qq < 4; ++qq) {
            int ww = qq * 2 + fh;
            s  += sst[(ww * 32 + ln) * 2 + 0];
            s2 += sst[(ww * 32 + ln) * 2 + 1];
        }
        int blk = b * NTILE1 + tile;
        g_part[(blk * FIL + tid) * 2 + 0] = s;
        g_part[(blk * FIL + tid) * 2 + 1] = s2;
    }
}

// ---------------- K2: reduce BN stats (UNCHANGED / validated) ----------------
extern "C" __global__ void k2_stats(const float* __restrict__ w2,
                                    const float* __restrict__ b2,
                                    const float* __restrict__ gamma,
                                    const float* __restrict__ beta) {
    __shared__ double ssum[256], ssum2[256];
    __shared__ float sct[FIL];
    int tid = threadIdx.x;  // 256
    int f = tid & 63, seg = tid >> 6;
    double s = 0.0, s2 = 0.0;
    for (int blk = seg; blk < NTILE1 * BATCH; blk += 4) {
        s  += (double)g_part[(blk * FIL + f) * 2 + 0];
        s2 += (double)g_part[(blk * FIL + f) * 2 + 1];
    }
    ssum[tid] = s; ssum2[tid] = s2;
    __syncthreads();
    if (seg == 0) {
        for (int k = 1; k < 4; ++k) { s += ssum[f + 64 * k]; s2 += ssum2[f + 64 * k]; }
        double N = (double)BATCH * (double)T2;
        double mud = s / N;
        float mu = (float)mud;
        float var = (float)(s2 / N - mud * mud);
        float scale = gamma[f] * rsqrtf(var + BN_EPSF);
        float shift = beta[f] - mu * scale;
        float wsum = 0.f;
        for (int k = 0; k < WIN; ++k) {
            float wv = w2[f * WIN + k];
            g_we2[f * WIN + k] = wv * scale;
            wsum += wv;
        }
        sct[f] = shift * wsum;
    }
    __syncthreads();
    if (tid == 0) {
        float c = b2[0];
        for (int i = 0; i < FIL; ++i) c += sct[i];
        g_cterm = c;
    }
}

// ---------------- K3: conv2 + relu + sigmoid + bucket index (R8 form) --------
extern "C" __global__ void k3_conv2_idx() {
    extern __shared__ float sm3[];
    float* sh  = sm3;                     // (TILE3+4)*65  layout [t][f] pad
    float* swe = sh + (TILE3 + 4) * 65;   // FIL*WIN
    __shared__ float sct;
    int tile = blockIdx.x, b = blockIdx.y;
    int t0 = tile * TILE3;
    int tid = threadIdx.x;  // 128

    for (int o = tid; o < (TILE3 + 4) * FIL; o += 128) {
        int tl = o >> 6, ff = o & 63;
        int t = t0 + tl;
        sh[tl * 65 + ff] = (t < T2) ? g_h2[((size_t)b * T2 + t) * FIL + ff] : 0.f;
    }
    for (int o = tid; o < FIL * WIN; o += 128) swe[o] = g_we2[o];
    if (tid == 0) sct = g_cterm;
    __syncthreads();

    int l = t0 + tid;
    if (l < LL) {
        float z = sct;
#pragma unroll 8
        for (int f = 0; f < FIL; ++f) {
            const float* hr = sh + tid * 65 + f;   // h[t=tid+k][f] at hr + 65k
            const float* wr = swe + f * WIN;
            z += wr[0] * hr[0] + wr[1] * hr[65] + wr[2] * hr[130]
               + wr[3] * hr[195] + wr[4] * hr[260];
        }
        z = fmaxf(z, 0.f);
        float c = 1.f / (1.f + expf(-z));
        int iv = (int)ceilf(c * 256.f) - 1;
        iv = max(0, min(255, iv));
        g_idx[b * LL + l] = iv;
    }
}

// ---------------- K4a: atomic-free per-quarter bucket scatter ----------------
// Block (q, b): 64 threads, thread a exclusively owns row a of a private smem
// G -> plain LDS/STS run-length RMW, no atomics. sidx chunk staged in smem.
// 256 blocks (vs 64) restores the parallelism the R8 version destroyed.
extern "C" __global__ void k4a_scatter() {
    extern __shared__ float s4a[];
    float* sG   = s4a;                      // 64*257
    int*  sidx  = (int*)(sG + 64 * 257);    // 512 (509 used)
    int*  shist = sidx + 512;               // 256
    int q = blockIdx.x, b = blockIdx.y;
    int tid = threadIdx.x;                  // 64
    int a = tid;
    int l0 = q * LQ;

    for (int o = tid; o < 64 * 257; o += 64) sG[o] = 0.f;
    for (int o = tid; o < 256; o += 64) shist[o] = 0;
    for (int o = tid; o < LQ; o += 64) sidx[o] = g_idx[b * LL + l0 + o];
    __syncthreads();

    {
        float* row = sG + a * 257;          // banks (a+j)%32: conflict-free
        int jprev = -1, cacc = 0;
        float wacc = 0.f;
#pragma unroll 8
        for (int i = 0; i < LQ; ++i) {
            int j = sidx[i];                        // broadcast LDS
            float wv = g_W1T[(l0 + i) * DA + a];    // coalesced LDG
            if (j != jprev) {                       // warp-uniform branch
                if (jprev >= 0) {
                    row[jprev] += wacc;
                    if (a == 0) shist[jprev] += cacc;
                }
                jprev = j; wacc = wv; cacc = 1;
            } else { wacc += wv; ++cacc; }
        }
        if (jprev >= 0) {
            row[jprev] += wacc;
            if (a == 0) shist[jprev] += cacc;
        }
    }
    __syncthreads();

    int blk = b * 4 + q;
    for (int o = tid; o < 64 * 256; o += 64) {
        int aa = o >> 8, j = o & 255;
        g_Gpart[((size_t)blk * DA + aa) * DD + j] = sG[aa * 257 + j];
    }
    for (int j = tid; j < 256; j += 64)
        g_hpart[blk * DD + j] = shist[j];
}

// ---------------- K4b: merge quarters + hist + scan compaction ---------------
extern "C" __global__ void k4b_merge() {
    __shared__ int shist[256];
    __shared__ int sscan[256];
    __shared__ int spos[256];
    int b = blockIdx.x;
    int tid = threadIdx.x;  // 256
    int j = tid;

    int c = 0;
#pragma unroll
    for (int q = 0; q < 4; ++q) c += g_hpart[(b * 4 + q) * DD + j];
    shist[j] = c;
    g_cnt[b * DD + j] = c;
    int cflag = (c > 0) ? 1 : 0;
    sscan[tid] = cflag;
    __syncthreads();
    for (int off = 1; off < 256; off <<= 1) {
        int add = (tid >= off) ? sscan[tid - off] : 0;
        __syncthreads();
        sscan[tid] += add;
        __syncthreads();
    }
    int pos = sscan[tid] - cflag;
    spos[tid] = pos;
    if (cflag) g_jlist[b * DD + pos] = tid;
    if (tid == 255) g_nact[b] = sscan[255];
    __syncthreads();

    for (int o = tid; o < DA * DD; o += 256) {
        int aa = o >> 8, jj = o & 255;
        if (shist[jj] > 0) {
            const float* gp = g_Gpart + ((size_t)(b * 4) * DA + aa) * DD + jj;
            float v = gp[0] + gp[(size_t)DA * DD] + gp[2 * (size_t)DA * DD]
                    + gp[3 * (size_t)DA * DD];
            g_Gc[((size_t)b * DD + spos[jj]) * DA + aa] = v;
        }
    }
}

// ---------------- K5: t = tanh(Gc @ emb_active); A = W2^T t ----------------
extern "C" __global__ void k5_gemm(const float* __restrict__ emb,
                                   const float* __restrict__ W2) {
    extern __shared__ float sm5[];
    float* sGT = sm5;                   // DD*JP (only nact rows used)
    float* sA  = sGT + DD * JP;         // 128
    float* sW2 = sA + 128;              // 64
    int*   sjl = (int*)(sW2 + DA);      // 256
    int b = blockIdx.x, half = blockIdx.y;
    int tid = threadIdx.x;  // 128

    int nact = g_nact[b];
    for (int o = tid; o < nact * DA; o += 128) {
        int jj = o >> 6, a = o & 63;
        sGT[jj * JP + a] = g_Gc[((size_t)b * DD + jj) * DA + a];
    }
    for (int o = tid; o < DD; o += 128) sjl[o] = g_jlist[b * DD + o];
    sA[tid] = 0.f;
    if (tid < DA) sW2[tid] = W2[tid];
    __syncthreads();

    int ta = tid >> 4, td = tid & 15;   // 8 x 16
    int a0 = ta * 8;
    int d0 = half * 128 + td * 8;
    float acc[8][8];
#pragma unroll
    for (int r = 0; r < 8; ++r)
#pragma unroll
        for (int s = 0; s < 8; ++s) acc[r][s] = 0.f;

    for (int jj = 0; jj < nact; ++jj) {
        const float* er = emb + (size_t)sjl[jj] * DD + d0;
        float4 ga = *(const float4*)&sGT[jj * JP + a0];
        float4 gb = *(const float4*)&sGT[jj * JP + a0 + 4];
        float4 e0 = __ldg((const float4*)er);
        float4 e1 = __ldg((const float4*)(er + 4));
        float gv[8] = {ga.x, ga.y, ga.z, ga.w, gb.x, gb.y, gb.z, gb.w};
        float ev[8] = {e0.x, e0.y, e0.z, e0.w, e1.x, e1.y, e1.z, e1.w};
#pragma unroll
        for (int r = 0; r < 8; ++r)
#pragma unroll
            for (int s = 0; s < 8; ++s)
                acc[r][s] = fmaf(gv[r], ev[s], acc[r][s]);
    }

    float pA[8];
#pragma unroll
    for (int s = 0; s < 8; ++s) pA[s] = 0.f;
#pragma unroll
    for (int r = 0; r < 8; ++r) {
        float wv = sW2[a0 + r];
#pragma unroll
        for (int s = 0; s < 8; ++s)
            pA[s] = fmaf(wv, tanhf(acc[r][s]), pA[s]);
    }
#pragma unroll
    for (int s = 0; s < 8; ++s)
        atomicAdd(&sA[td * 8 + s], pA[s]);
    __syncthreads();
    g_A[b * DD + half * 128 + tid] = sA[tid];
}

// ---------------- K6: bucket softmax + att gather + scores ----------------
extern "C" __global__ void k6_final(const float* __restrict__ emb,
                                    const float* __restrict__ lin_w,
                                    const float* __restrict__ lin_b,
                                    float* __restrict__ out) {
    __shared__ float sA[DD];
    __shared__ float sE[DD];
    __shared__ float red[256];
    int b = blockIdx.x;
    int tid = threadIdx.x;  // 256
    sA[tid] = g_A[b * DD + tid];
    __syncthreads();

    int j = tid;
    float P = 0.f;
    const float4* er = (const float4*)(emb + (size_t)j * DD);
#pragma unroll 8
    for (int d4 = 0; d4 < DD / 4; ++d4) {
        float4 e = __ldg(er + d4);
        P += e.x * sA[d4 * 4 + 0] + e.y * sA[d4 * 4 + 1]
           + e.z * sA[d4 * 4 + 2] + e.w * sA[d4 * 4 + 3];
    }
    int cj = g_cnt[b * DD + j];
    red[tid] = (cj > 0) ? P : -3.0e38f;
    __syncthreads();
    for (int st = 128; st > 0; st >>= 1) {
        if (tid < st) red[tid] = fmaxf(red[tid], red[tid + st]);
        __syncthreads();
    }
    float m = red[0];
    __syncthreads();
    float ex = (cj > 0) ? expf(P - m) : 0.f;
    red[tid] = (float)cj * ex;
    __syncthreads();
    for (int st = 128; st > 0; st >>= 1) {
        if (tid < st) red[tid] += red[tid + st];
        __syncthreads();
    }
    float Z = red[0];
    sE[j] = ex / Z;
    __syncthreads();

    for (int l = tid; l < LL; l += 256)
        out[b * LL + l] = sE[g_idx[b * LL + l]];

    if (tid < SEC) {
        float s = lin_b[tid];
        const float* wr = lin_w + tid * DD;
        for (int d = 0; d < DD; ++d) s += wr[d] * sA[d];
        out[BATCH * LL + b * SEC + tid] = s;
    }
}

// ---------------- launch ----------------
extern "C" void kernel_launch(void* const* d_in, const int* in_sizes, int n_in,
                              void* d_out, int out_size) {
    const float* x     = (const float*)d_in[0];
    const float* c1w   = (const float*)d_in[1];
    const float* c1b   = (const float*)d_in[2];
    const float* gamma = (const float*)d_in[3];
    const float* beta  = (const float*)d_in[4];
    const float* c2w   = (const float*)d_in[5];
    const float* c2b   = (const float*)d_in[6];
    const float* emb   = (const float*)d_in[7];
    const float* W1    = (const float*)d_in[8];
    const float* W2    = (const float*)d_in[9];
    const float* lw    = (const float*)d_in[10];
    const float* lb    = (const float*)d_in[11];
    float* out = (float*)d_out;

    size_t sm1  = (size_t)(CIN * INT_ + 8 * 32 * 2) * sizeof(float);
    size_t sm3  = (size_t)((TILE3 + 4) * 65 + FIL * WIN) * sizeof(float);
    size_t sm4a = (size_t)(64 * 257) * sizeof(float) + (512 + 256) * sizeof(int);
    size_t sm5  = (size_t)(DD * JP + 128 + DA) * sizeof(float) + DD * sizeof(int);
    cudaFuncSetAttribute(k1_conv_pool, cudaFuncAttributeMaxDynamicSharedMemorySize, (int)sm1);
    cudaFuncSetAttribute(k3_conv2_idx, cudaFuncAttributeMaxDynamicSharedMemorySize, (int)sm3);
    cudaFuncSetAttribute(k4a_scatter,  cudaFuncAttributeMaxDynamicSharedMemorySize, (int)sm4a);
    cudaFuncSetAttribute(k5_gemm,      cudaFuncAttributeMaxDynamicSharedMemorySize, (int)sm5);

    int n0 = LL * DA + CIN * WIN * FIL;
    k0_prep<<<(n0 + 255) / 256, 256>>>(W1, c1w);
    k1_conv_pool<<<dim3(NTILE1, BATCH), 256, sm1>>>(x, c1b);
    k2_stats<<<1, 256>>>(c2w, c2b, gamma, beta);
    k3_conv2_idx<<<dim3(NTILE3, BATCH), 128, sm3>>>();
    k4a_scatter<<<dim3(4, BATCH), 64, sm4a>>>();
    k4b_merge<<<BATCH, 256>>>();
    k5_gemm<<<dim3(BATCH, 2), 128, sm5>>>(emb, W2);
    k6_final<<<BATCH, 256>>>(emb, lw, lb, out);
}

// round 11
// speedup vs baseline: 1.2997x; 1.1014x over previous
#include <cuda_runtime.h>
#include <math.h>

#define BATCH 64
#define CIN 32
#define T_IN 2048
#define FIL 64
#define WIN 5
#define T1 2044
#define T2 2040
#define LL 2036
#define DA 64
#define DD 256
#define SEC 11
#define BN_EPSF 1e-5f

#define TILE 128        // pooled outputs per k1 block
#define INT_ 136        // input positions per k1 tile
#define NTILE1 16       // k1 tiles over T2
#define TILE3 128       // l positions per k3 block
#define NTILE3 16       // k3 tiles over LL
#define SH3 68          // float4-alignable [t][f] stride in k3
#define JP 68           // padded a-stride for sGT in k5

// ---------------- scratch (device globals) ----------------
__device__ float g_h2[BATCH * T2 * FIL];            // pooled conv1 out, [b][t][f]
__device__ float g_part[NTILE1 * BATCH * FIL * 2];  // per-block BN partials
__device__ float g_we2[FIL * WIN];
__device__ float g_cterm;
__device__ int   g_idx[BATCH * LL];
__device__ float g_W1T[LL * DA];                    // W1 transposed [l][a]
__device__ float g_w1T[CIN * WIN * FIL];            // conv1 w transposed [c][k][f]
__device__ float g_Gc[BATCH * DD * DA];             // compact G [b][jj][a]
__device__ int   g_jlist[BATCH * DD];
__device__ int   g_nact[BATCH];
__device__ int   g_cnt[BATCH * DD];
__device__ float g_A[BATCH * DD];

// ---------------- K0: transposes ----------------
extern "C" __global__ void k0_prep(const float* __restrict__ W1,
                                   const float* __restrict__ w1) {
    int t = blockIdx.x * 256 + threadIdx.x;
    if (t < LL * DA) {
        int l = t >> 6, a = t & 63;
        g_W1T[t] = W1[a * LL + l];
    }
    int u = t - LL * DA;
    if (u >= 0 && u < CIN * WIN * FIL) {
        int f = u & 63, ck = u >> 6;          // ck = c*5+k
        g_w1T[u] = w1[f * (CIN * WIN) + ck];
    }
}

// ---------------- K1: conv1 + maxpool5 + BN partials ------------------------
// Arithmetic BITWISE IDENTICAL to validated R7. Direct register->global pooled
// store (no staging smem, one fewer sync). __launch_bounds__(256,3) RESTORED —
// dropping it in R10 let ptxas blow past the 3-CTA/SM register budget.
extern "C" __global__ void __launch_bounds__(256, 3)
k1_conv_pool(const float* __restrict__ x, const float* __restrict__ b1) {
    extern __shared__ float sm[];
    float* sx  = sm;                    // CIN*INT_  (4352)
    float* sst = sx + CIN * INT_;       // 8*32*2    (512)

    int tile = blockIdx.x, b = blockIdx.y;
    int t0 = tile * TILE;
    int tid = threadIdx.x;
    int w = tid >> 5, lane = tid & 31;
    int q = w >> 1, fhi = w & 1;
    int f = fhi * 32 + lane;
    int npool = min(TILE, T2 - t0);

    for (int i = tid; i < CIN * INT_; i += 256) {
        int c = i / INT_, p = i - c * INT_;
        int g = t0 + p;
        sx[i] = (g < T_IN) ? x[(b * CIN + c) * T_IN + g] : 0.f;
    }
    __syncthreads();

    float acc[36];
    float bias = __ldg(&b1[f]);
#pragma unroll
    for (int i = 0; i < 36; ++i) acc[i] = bias;

    int base = q * 32;
    for (int c = 0; c < CIN; ++c) {
        const float* wr = g_w1T + c * WIN * FIL + f;
        float w0 = __ldg(wr), wa = __ldg(wr + FIL), wb = __ldg(wr + 2 * FIL),
              wc = __ldg(wr + 3 * FIL), wd = __ldg(wr + 4 * FIL);
        const float* xr = sx + c * INT_ + base;
        float x0 = xr[0], x1 = xr[1], x2 = xr[2], x3 = xr[3];
#pragma unroll
        for (int i = 0; i < 36; ++i) {
            float x4 = xr[i + 4];
            acc[i] += w0 * x0 + wa * x1 + wb * x2 + wc * x3 + wd * x4;
            x0 = x1; x1 = x2; x2 = x3; x3 = x4;
        }
    }

    // pool + stats in registers; direct coalesced store (lanes -> 128B STG)
    float ls = 0.f, ls2 = 0.f;
    float* h2row = g_h2 + ((size_t)b * T2 + t0) * FIL + f;
#pragma unroll
    for (int i = 0; i < 32; ++i) {
        float m = acc[i];
        m = fmaxf(m, acc[i + 1]); m = fmaxf(m, acc[i + 2]);
        m = fmaxf(m, acc[i + 3]); m = fmaxf(m, acc[i + 4]);
        int p = base + i;
        if (p < npool) {
            h2row[(size_t)p * FIL] = m;
            ls += m; ls2 += m * m;
        }
    }
    sst[(w * 32 + lane) * 2 + 0] = ls;
    sst[(w * 32 + lane) * 2 + 1] = ls2;
    __syncthreads();

    if (tid < FIL) {
        int fh = tid >> 5, ln = tid & 31;
        float s = 0.f, s2 = 0.f;
        for (int qq = 0; qq < 4; ++qq) {
            int ww = qq * 2 + fh;
            s  += sst[(ww * 32 + ln) * 2 + 0];
            s2 += sst[(ww * 32 + ln) * 2 + 1];
        }
        int blk = b * NTILE1 + tile;
        g_part[(blk * FIL + tid) * 2 + 0] = s;
        g_part[(blk * FIL + tid) * 2 + 1] = s2;
    }
}

// ---------------- K2: reduce BN stats (UNCHANGED / validated) ----------------
extern "C" __global__ void k2_stats(const float* __restrict__ w2,
                                    const float* __restrict__ b2,
                                    const float* __restrict__ gamma,
                                    const float* __restrict__ beta) {
    __shared__ double ssum[256], ssum2[256];
    __shared__ float sct[FIL];
    int tid = threadIdx.x;  // 256
    int f = tid & 63, seg = tid >> 6;
    double s = 0.0, s2 = 0.0;
    for (int blk = seg; blk < NTILE1 * BATCH; blk += 4) {
        s  += (double)g_part[(blk * FIL + f) * 2 + 0];
        s2 += (double)g_part[(blk * FIL + f) * 2 + 1];
    }
    ssum[tid] = s; ssum2[tid] = s2;
    __syncthreads();
    if (seg == 0) {
        for (int k = 1; k < 4; ++k) { s += ssum[f + 64 * k]; s2 += ssum2[f + 64 * k]; }
        double N = (double)BATCH * (double)T2;
        double mud = s / N;
        float mu = (float)mud;
        float var = (float)(s2 / N - mud * mud);
        float scale = gamma[f] * rsqrtf(var + BN_EPSF);
        float shift = beta[f] - mu * scale;
        float wsum = 0.f;
        for (int k = 0; k < WIN; ++k) {
            float wv = w2[f * WIN + k];
            g_we2[f * WIN + k] = wv * scale;
            wsum += wv;
        }
        sct[f] = shift * wsum;
    }
    __syncthreads();
    if (tid == 0) {
        float c = b2[0];
        for (int i = 0; i < FIL; ++i) c += sct[i];
        g_cterm = c;
    }
}

// ---------------- K3: conv2 + relu + sigmoid + bucket index ------------------
// Vector-load version: stride 68 [t][f] smem (float4-alignable), swe re-laid
// as [k][f]. Per-f expression SHAPE unchanged (z += w0*h0+w1*h1+w2*h2+w3*h3
// +w4*h4, sequential in f) -> same fma contraction, same buckets; only the
// operand loads are vectorized (160 LDS.128 vs 640 scalar LDS per thread).
extern "C" __global__ void k3_conv2_idx() {
    extern __shared__ float sm3[];
    float* sh   = sm3;                      // (TILE3+4)*SH3
    float* swe2 = sh + (TILE3 + 4) * SH3;   // WIN*FIL  layout [k][f]
    __shared__ float sct;
    int tile = blockIdx.x, b = blockIdx.y;
    int t0 = tile * TILE3;
    int tid = threadIdx.x;  // 128

    for (int o = tid; o < (TILE3 + 4) * FIL; o += 128) {
        int tl = o >> 6, ff = o & 63;
        int t = t0 + tl;
        sh[tl * SH3 + ff] = (t < T2) ? g_h2[((size_t)b * T2 + t) * FIL + ff] : 0.f;
    }
    for (int o = tid; o < FIL * WIN; o += 128) {
        int ff = o & 63, k = o >> 6;     // o = k*64+ff
        swe2[k * FIL + ff] = g_we2[ff * WIN + k];
    }
    if (tid == 0) sct = g_cterm;
    __syncthreads();

    int l = t0 + tid;
    if (l < LL) {
        float z = sct;
        const float* hb = sh + tid * SH3;
#pragma unroll 4
        for (int f = 0; f < FIL; f += 4) {
            float4 h0 = *(const float4*)(hb + f);
            float4 h1 = *(const float4*)(hb + SH3 + f);
            float4 h2 = *(const float4*)(hb + 2 * SH3 + f);
            float4 h3 = *(const float4*)(hb + 3 * SH3 + f);
            float4 h4 = *(const float4*)(hb + 4 * SH3 + f);
            float4 w0 = *(const float4*)(swe2 + f);
            float4 w1 = *(const float4*)(swe2 + FIL + f);
            float4 w2 = *(const float4*)(swe2 + 2 * FIL + f);
            float4 w3 = *(const float4*)(swe2 + 3 * FIL + f);
            float4 w4 = *(const float4*)(swe2 + 4 * FIL + f);
            z += w0.x * h0.x + w1.x * h1.x + w2.x * h2.x + w3.x * h3.x + w4.x * h4.x;
            z += w0.y * h0.y + w1.y * h1.y + w2.y * h2.y + w3.y * h3.y + w4.y * h4.y;
            z += w0.z * h0.z + w1.z * h1.z + w2.z * h2.z + w3.z * h3.z + w4.z * h4.z;
            z += w0.w * h0.w + w1.w * h1.w + w2.w * h2.w + w3.w * h3.w + w4.w * h4.w;
        }
        z = fmaxf(z, 0.f);
        float c = 1.f / (1.f + expf(-z));
        int iv = (int)ceilf(c * 256.f) - 1;
        iv = max(0, min(255, iv));
        g_idx[b * LL + l] = iv;
    }
}

// ---------------- K4: run-length bucket scatter + compaction -----------------
// EXACT R7 version (validated inside the 330us run). 256 threads, shared
// atomics with run-length coalescing, scan compaction.
extern "C" __global__ void k4_scatter() {
    extern __shared__ float sm4[];
    float* sG   = sm4;                         // DA*257
    int* shist  = (int*)(sG + DA * 257);       // 256
    int* sscan  = shist + 256;                 // 256
    int* spos   = sscan + 256;                 // 256
    int b = blockIdx.x;
    int tid = threadIdx.x;  // 256
    for (int o = tid; o < DA * 257; o += 256) sG[o] = 0.f;
    shist[tid] = 0;
    __syncthreads();

    int a = tid & 63, q = tid >> 6;
    int l0 = q * 509, l1 = l0 + 509;           // 4*509 = 2036
    int jprev = -1, cacc = 0;
    float wacc = 0.f;
    for (int l = l0; l < l1; ++l) {
        int j = g_idx[b * LL + l];
        float wv = g_W1T[l * DA + a];
        if (j != jprev) {
            if (jprev >= 0) {
                atomicAdd(&sG[a * 257 + jprev], wacc);
                if (a == 0) atomicAdd(&shist[jprev], cacc);
            }
            jprev = j; wacc = wv; cacc = 1;
        } else { wacc += wv; ++cacc; }
    }
    if (jprev >= 0) {
        atomicAdd(&sG[a * 257 + jprev], wacc);
        if (a == 0) atomicAdd(&shist[jprev], cacc);
    }
    __syncthreads();

    int cflag = (shist[tid] > 0) ? 1 : 0;
    sscan[tid] = cflag;
    __syncthreads();
    for (int off = 1; off < 256; off <<= 1) {
        int add = (tid >= off) ? sscan[tid - off] : 0;
        __syncthreads();
        sscan[tid] += add;
        __syncthreads();
    }
    int pos = sscan[tid] - cflag;
    spos[tid] = pos;
    if (cflag) g_jlist[b * DD + pos] = tid;
    if (tid == 255) g_nact[b] = sscan[255];
    g_cnt[b * DD + tid] = shist[tid];
    __syncthreads();

    for (int o = tid; o < DD * DA; o += 256) {
        int j = o >> 6, aa = o & 63;
        if (shist[j] > 0)
            g_Gc[((size_t)b * DD + spos[j]) * DA + aa] = sG[aa * 257 + j];
    }
}

// ---------------- K5: t = tanh(Gc @ emb_active); A = W2^T t ----------------
extern "C" __global__ void k5_gemm(const float* __restrict__ emb,
                                   const float* __restrict__ W2) {
    extern __shared__ float sm5[];
    float* sGT = sm5;                   // DD*JP (only nact rows used)
    float* sA  = sGT + DD * JP;         // 128
    float* sW2 = sA + 128;              // 64
    int*   sjl = (int*)(sW2 + DA);      // 256
    int b = blockIdx.x, half = blockIdx.y;
    int tid = threadIdx.x;  // 128

    int nact = g_nact[b];
    for (int o = tid; o < nact * DA; o += 128) {
        int jj = o >> 6, a = o & 63;
        sGT[jj * JP + a] = g_Gc[((size_t)b * DD + jj) * DA + a];
    }
    for (int o = tid; o < DD; o += 128) sjl[o] = g_jlist[b * DD + o];
    sA[tid] = 0.f;
    if (tid < DA) sW2[tid] = W2[tid];
    __syncthreads();

    int ta = tid >> 4, td = tid & 15;   // 8 x 16
    int a0 = ta * 8;
    int d0 = half * 128 + td * 8;
    float acc[8][8];
#pragma unroll
    for (int r = 0; r < 8; ++r)
#pragma unroll
        for (int s = 0; s < 8; ++s) acc[r][s] = 0.f;

    for (int jj = 0; jj < nact; ++jj) {
        const float* er = emb + (size_t)sjl[jj] * DD + d0;
        float4 ga = *(const float4*)&sGT[jj * JP + a0];
        float4 gb = *(const float4*)&sGT[jj * JP + a0 + 4];
        float4 e0 = __ldg((const float4*)er);
        float4 e1 = __ldg((const float4*)(er + 4));
        float gv[8] = {ga.x, ga.y, ga.z, ga.w, gb.x, gb.y, gb.z, gb.w};
        float ev[8] = {e0.x, e0.y, e0.z, e0.w, e1.x, e1.y, e1.z, e1.w};
#pragma unroll
        for (int r = 0; r < 8; ++r)
#pragma unroll
            for (int s = 0; s < 8; ++s)
                acc[r][s] = fmaf(gv[r], ev[s], acc[r][s]);
    }

    float pA[8];
#pragma unroll
    for (int s = 0; s < 8; ++s) pA[s] = 0.f;
#pragma unroll
    for (int r = 0; r < 8; ++r) {
        float wv = sW2[a0 + r];
#pragma unroll
        for (int s = 0; s < 8; ++s)
            pA[s] = fmaf(wv, tanhf(acc[r][s]), pA[s]);
    }
#pragma unroll
    for (int s = 0; s < 8; ++s)
        atomicAdd(&sA[td * 8 + s], pA[s]);
    __syncthreads();
    g_A[b * DD + half * 128 + tid] = sA[tid];
}

// ---------------- K6: bucket softmax + att gather + scores ----------------
extern "C" __global__ void k6_final(const float* __restrict__ emb,
                                    const float* __restrict__ lin_w,
                                    const float* __restrict__ lin_b,
                                    float* __restrict__ out) {
    __shared__ float sA[DD];
    __shared__ float sE[DD];
    __shared__ float red[256];
    int b = blockIdx.x;
    int tid = threadIdx.x;  // 256
    sA[tid] = g_A[b * DD + tid];
    __syncthreads();

    int j = tid;
    float P = 0.f;
    const float4* er = (const float4*)(emb + (size_t)j * DD);
#pragma unroll 8
    for (int d4 = 0; d4 < DD / 4; ++d4) {
        float4 e = __ldg(er + d4);
        P += e.x * sA[d4 * 4 + 0] + e.y * sA[d4 * 4 + 1]
           + e.z * sA[d4 * 4 + 2] + e.w * sA[d4 * 4 + 3];
    }
    int cj = g_cnt[b * DD + j];
    red[tid] = (cj > 0) ? P : -3.0e38f;
    __syncthreads();
    for (int st = 128; st > 0; st >>= 1) {
        if (tid < st) red[tid] = fmaxf(red[tid], red[tid + st]);
        __syncthreads();
    }
    float m = red[0];
    __syncthreads();
    float ex = (cj > 0) ? expf(P - m) : 0.f;
    red[tid] = (float)cj * ex;
    __syncthreads();
    for (int st = 128; st > 0; st >>= 1) {
        if (tid < st) red[tid] += red[tid + st];
        __syncthreads();
    }
    float Z = red[0];
    sE[j] = ex / Z;
    __syncthreads();

    for (int l = tid; l < LL; l += 256)
        out[b * LL + l] = sE[g_idx[b * LL + l]];

    if (tid < SEC) {
        float s = lin_b[tid];
        const float* wr = lin_w + tid * DD;
        for (int d = 0; d < DD; ++d) s += wr[d] * sA[d];
        out[BATCH * LL + b * SEC + tid] = s;
    }
}

// ---------------- launch ----------------
extern "C" void kernel_launch(void* const* d_in, const int* in_sizes, int n_in,
                              void* d_out, int out_size) {
    const float* x     = (const float*)d_in[0];
    const float* c1w   = (const float*)d_in[1];
    const float* c1b   = (const float*)d_in[2];
    const float* gamma = (const float*)d_in[3];
    const float* beta  = (const float*)d_in[4];
    const float* c2w   = (const float*)d_in[5];
    const float* c2b   = (const float*)d_in[6];
    const float* emb   = (const float*)d_in[7];
    const float* W1    = (const float*)d_in[8];
    const float* W2    = (const float*)d_in[9];
    const float* lw    = (const float*)d_in[10];
    const float* lb    = (const float*)d_in[11];
    float* out = (float*)d_out;

    size_t sm1 = (size_t)(CIN * INT_ + 8 * 32 * 2) * sizeof(float);
    size_t sm3 = (size_t)((TILE3 + 4) * SH3 + WIN * FIL) * sizeof(float);
    size_t sm4 = (size_t)DA * 257 * sizeof(float) + 3 * 256 * sizeof(int);
    size_t sm5 = (size_t)(DD * JP + 128 + DA) * sizeof(float) + DD * sizeof(int);
    cudaFuncSetAttribute(k1_conv_pool, cudaFuncAttributeMaxDynamicSharedMemorySize, (int)sm1);
    cudaFuncSetAttribute(k3_conv2_idx, cudaFuncAttributeMaxDynamicSharedMemorySize, (int)sm3);
    cudaFuncSetAttribute(k4_scatter,   cudaFuncAttributeMaxDynamicSharedMemorySize, (int)sm4);
    cudaFuncSetAttribute(k5_gemm,      cudaFuncAttributeMaxDynamicSharedMemorySize, (int)sm5);

    int n0 = LL * DA + CIN * WIN * FIL;
    k0_prep<<<(n0 + 255) / 256, 256>>>(W1, c1w);
    k1_conv_pool<<<dim3(NTILE1, BATCH), 256, sm1>>>(x, c1b);
    k2_stats<<<1, 256>>>(c2w, c2b, gamma, beta);
    k3_conv2_idx<<<dim3(NTILE3, BATCH), 128, sm3>>>();
    k4_scatter<<<BATCH, 256, sm4>>>();
    k5_gemm<<<dim3(BATCH, 2), 128, sm5>>>(emb, W2);
    k6_final<<<BATCH, 256>>>(emb, lw, lb, out);
}